// round 10
// baseline (speedup 1.0000x reference)
#include <cuda_runtime.h>
#include <cuda_bf16.h>
#include <cstdint>

#define N_NODES 50000
#define N_EDGES_MAX 600000
#define D_FEAT 128
#define HIDDEN 128
#define OUT_D 64

#define LDA 136                      // padded bf16 row (128 + 8)
#define TS  (128 * LDA * 2)          // one smem tile: 34816 B
#define SM_TOTAL (3 * TS)            // Ah, Al, B = 104448 B -> 2 CTAs/SM

#define CHUNK 256
#define NCHUNK ((N_NODES + CHUNK - 1) / CHUNK)   // 196

// ---------------- device scratch (no allocs allowed) ----------------
__device__ float g_mean1[N_NODES * D_FEAT];   // layer-1 neighbor mean
__device__ float g_t[N_NODES * OUT_D];        // h @ W2l (pre-aggregation)
__device__ float g_hr[N_NODES * OUT_D];       // h @ W2r (root term)
__device__ int   g_is64;

// CSR structure (built per call, dst-sorted)
__device__ int g_deg[N_NODES];
__device__ int g_rowptr[N_NODES + 1];
__device__ int g_pos[N_NODES];
__device__ int g_csr_src[N_EDGES_MAX];
__device__ int g_chunksum[NCHUNK];
__device__ int g_chunkoff[NCHUNK];

// pre-split weights, [n][k] layout
__device__ __align__(16) __nv_bfloat16 g_W1l_hi[16384], g_W1l_lo[16384];
__device__ __align__(16) __nv_bfloat16 g_W1r_hi[16384], g_W1r_lo[16384];
__device__ __align__(16) __nv_bfloat16 g_W2_hi[16384],  g_W2_lo[16384];

// ---------------- helpers ----------------
__device__ __forceinline__ uint32_t smem_u32(const void* p) {
    uint32_t a;
    asm("{ .reg .u64 t; cvta.to.shared.u64 t, %1; cvt.u32.u64 %0, t; }"
        : "=r"(a) : "l"(p));
    return a;
}

__device__ __forceinline__ void ldm_x4(uint32_t* r, uint32_t addr) {
    asm volatile("ldmatrix.sync.aligned.m8n8.x4.shared.b16 {%0,%1,%2,%3}, [%4];"
                 : "=r"(r[0]), "=r"(r[1]), "=r"(r[2]), "=r"(r[3]) : "r"(addr));
}
__device__ __forceinline__ void mma16816(float* d, const uint32_t* a, const uint32_t* b) {
    asm volatile(
        "mma.sync.aligned.m16n8k16.row.col.f32.bf16.bf16.f32 "
        "{%0,%1,%2,%3},{%4,%5,%6,%7},{%8,%9},{%0,%1,%2,%3};"
        : "+f"(d[0]), "+f"(d[1]), "+f"(d[2]), "+f"(d[3])
        : "r"(a[0]), "r"(a[1]), "r"(a[2]), "r"(a[3]), "r"(b[0]), "r"(b[1]));
}

// one full K=128 pass of the 128x128 tile: warp (m_base, n_base) 32x64
__device__ __forceinline__ void mma_tile(uint32_t aBase, uint32_t bBase,
                                         float acc[2][8][4], int lane,
                                         int m_base, int n_base) {
    uint32_t aRow = aBase + (((m_base + (lane & 15)) * LDA + ((lane >> 4) << 3)) << 1);
    int bj = ((lane >> 4) & 1) * 8;
    int bk = ((lane >> 3) & 1) * 8;
    uint32_t bRow = bBase + (((n_base + bj + (lane & 7)) * LDA + bk) << 1);
#pragma unroll
    for (int k0 = 0; k0 < 128; k0 += 16) {
        uint32_t a0[4], a1[4];
        ldm_x4(a0, aRow + (k0 << 1));
        ldm_x4(a1, aRow + ((16 * LDA + k0) << 1));
        uint32_t b[8][2];
#pragma unroll
        for (int jp = 0; jp < 4; jp++) {
            uint32_t bb[4];
            ldm_x4(bb, bRow + ((jp * 16 * LDA + k0) << 1));
            b[jp * 2][0] = bb[0]; b[jp * 2][1] = bb[1];
            b[jp * 2 + 1][0] = bb[2]; b[jp * 2 + 1][1] = bb[3];
        }
#pragma unroll
        for (int j = 0; j < 8; j++) {
            mma16816(acc[0][j], a0, b[j]);
            mma16816(acc[1][j], a1, b[j]);
        }
    }
}

__device__ __forceinline__ void split_store(char* baseH, char* baseL, uint32_t off, float4 v) {
    __nv_bfloat162 h01, h23, l01, l23;
    __nv_bfloat16 h;
    h = __float2bfloat16(v.x); h01.x = h; l01.x = __float2bfloat16(v.x - __bfloat162float(h));
    h = __float2bfloat16(v.y); h01.y = h; l01.y = __float2bfloat16(v.y - __bfloat162float(h));
    h = __float2bfloat16(v.z); h23.x = h; l23.x = __float2bfloat16(v.z - __bfloat162float(h));
    h = __float2bfloat16(v.w); h23.y = h; l23.y = __float2bfloat16(v.w - __bfloat162float(h));
    *(uint2*)(baseH + off) = make_uint2(*(uint32_t*)&h01, *(uint32_t*)&h23);
    *(uint2*)(baseL + off) = make_uint2(*(uint32_t*)&l01, *(uint32_t*)&l23);
}

// ---------------- small kernels ----------------
__global__ void init_kernel(const int* __restrict__ idx) {
    int i = blockIdx.x * blockDim.x + threadIdx.x;
    if (i < N_NODES) g_deg[i] = 0;
    if (i == 0) {
        int ok = 1;
        for (int k = 0; k < 32; k++)
            if (idx[2 * k + 1] != 0) ok = 0;
        g_is64 = ok;
    }
}

__global__ void hist_kernel(const void* __restrict__ ei, int E) {
    int e = blockIdx.x * blockDim.x + threadIdx.x;
    if (e >= E) return;
    int d;
    if (g_is64) d = (int)((const long long*)ei)[E + e];
    else        d = ((const int*)ei)[E + e];
    atomicAdd(&g_deg[d], 1);
}

// ---- parallel 3-stage scan ----
// stage 1: per-chunk (256 degrees) sum
__global__ void chunkred_kernel() {
    __shared__ int sh[CHUNK];
    int i = blockIdx.x * CHUNK + threadIdx.x;
    sh[threadIdx.x] = (i < N_NODES) ? g_deg[i] : 0;
    __syncthreads();
    for (int off = CHUNK / 2; off > 0; off >>= 1) {
        if (threadIdx.x < off) sh[threadIdx.x] += sh[threadIdx.x + off];
        __syncthreads();
    }
    if (threadIdx.x == 0) g_chunksum[blockIdx.x] = sh[0];
}

// stage 2: single block scans NCHUNK chunk sums (exclusive)
__global__ void chunkscan_kernel() {
    __shared__ int sh[256];
    int t = threadIdx.x;
    sh[t] = (t < NCHUNK) ? g_chunksum[t] : 0;
    __syncthreads();
    for (int off = 1; off < 256; off <<= 1) {
        int v = (t >= off) ? sh[t - off] : 0;
        __syncthreads();
        sh[t] += v;
        __syncthreads();
    }
    if (t < NCHUNK) g_chunkoff[t] = (t == 0) ? 0 : sh[t - 1];
    if (t == 255) g_rowptr[N_NODES] = sh[NCHUNK - 1];
}

// stage 3: per-chunk exclusive scan + chunk offset -> rowptr, pos
__global__ void rowptr_kernel() {
    __shared__ int sh[CHUNK];
    int t = threadIdx.x;
    int i = blockIdx.x * CHUNK + t;
    int v = (i < N_NODES) ? g_deg[i] : 0;
    sh[t] = v;
    __syncthreads();
    for (int off = 1; off < CHUNK; off <<= 1) {
        int u = (t >= off) ? sh[t - off] : 0;
        __syncthreads();
        sh[t] += u;
        __syncthreads();
    }
    if (i < N_NODES) {
        int r = g_chunkoff[blockIdx.x] + sh[t] - v;   // exclusive
        g_rowptr[i] = r;
        g_pos[i] = r;
    }
}

__global__ void fill_kernel(const void* __restrict__ ei, int E) {
    int e = blockIdx.x * blockDim.x + threadIdx.x;
    if (e >= E) return;
    int s, d;
    if (g_is64) {
        const long long* p = (const long long*)ei;
        s = (int)p[e]; d = (int)p[E + e];
    } else {
        const int* p = (const int*)ei;
        s = p[e]; d = p[E + e];
    }
    int pos = atomicAdd(&g_pos[d], 1);
    g_csr_src[pos] = s;
}

__global__ void wprep_kernel(const float* __restrict__ W1l, const float* __restrict__ W1r,
                             const float* __restrict__ W2l, const float* __restrict__ W2r) {
    int i = blockIdx.x * blockDim.x + threadIdx.x;
    if (i >= 16384) return;
    int n = i >> 7, k = i & 127;
    float v = W1l[k * 128 + n];
    __nv_bfloat16 h = __float2bfloat16(v);
    g_W1l_hi[i] = h; g_W1l_lo[i] = __float2bfloat16(v - __bfloat162float(h));
    v = W1r[k * 128 + n];
    h = __float2bfloat16(v);
    g_W1r_hi[i] = h; g_W1r_lo[i] = __float2bfloat16(v - __bfloat162float(h));
    v = (n < 64) ? W2l[k * 64 + n] : W2r[k * 64 + (n - 64)];
    h = __float2bfloat16(v);
    g_W2_hi[i] = h; g_W2_lo[i] = __float2bfloat16(v - __bfloat162float(h));
}

// ---------------- gather-aggregate layer 1: warp per node, writes mean ----------------
__global__ void __launch_bounds__(256) gather1_kernel(const float* __restrict__ x) {
    int node = blockIdx.x * 8 + (threadIdx.x >> 5);
    if (node >= N_NODES) return;
    int lane = threadIdx.x & 31;
    int beg = g_rowptr[node], end = g_rowptr[node + 1];
    float4 s = make_float4(0.f, 0.f, 0.f, 0.f);
    int e = beg;
    for (; e + 2 <= end; e += 2) {
        int s0 = g_csr_src[e], s1 = g_csr_src[e + 1];
        float4 v0 = ((const float4*)(x + (size_t)s0 * D_FEAT))[lane];
        float4 v1 = ((const float4*)(x + (size_t)s1 * D_FEAT))[lane];
        s.x += v0.x + v1.x; s.y += v0.y + v1.y;
        s.z += v0.z + v1.z; s.w += v0.w + v1.w;
    }
    if (e < end) {
        int s0 = g_csr_src[e];
        float4 v0 = ((const float4*)(x + (size_t)s0 * D_FEAT))[lane];
        s.x += v0.x; s.y += v0.y; s.z += v0.z; s.w += v0.w;
    }
    float inv = 1.0f / (float)max(end - beg, 1);
    ((float4*)(g_mean1 + (size_t)node * D_FEAT))[lane] =
        make_float4(s.x * inv, s.y * inv, s.z * inv, s.w * inv);
}

// ---------------- gather-aggregate layer 2 + final epilogue ----------------
__global__ void __launch_bounds__(256) gather2_kernel(const float* __restrict__ b2l,
                                                      float* __restrict__ out) {
    int node = blockIdx.x * 8 + (threadIdx.x >> 5);
    if (node >= N_NODES) return;
    int lane = threadIdx.x & 31;
    int beg = g_rowptr[node], end = g_rowptr[node + 1];
    float2 s = make_float2(0.f, 0.f);
    int e = beg;
    for (; e + 2 <= end; e += 2) {
        int s0 = g_csr_src[e], s1 = g_csr_src[e + 1];
        float2 v0 = ((const float2*)(g_t + (size_t)s0 * OUT_D))[lane];
        float2 v1 = ((const float2*)(g_t + (size_t)s1 * OUT_D))[lane];
        s.x += v0.x + v1.x; s.y += v0.y + v1.y;
    }
    if (e < end) {
        int s0 = g_csr_src[e];
        float2 v0 = ((const float2*)(g_t + (size_t)s0 * OUT_D))[lane];
        s.x += v0.x; s.y += v0.y;
    }
    float inv = 1.0f / (float)max(end - beg, 1);
    float2 r = ((const float2*)(g_hr + (size_t)node * OUT_D))[lane];
    float2 b = ((const float2*)b2l)[lane];
    float2 o = make_float2(s.x * inv + b.x + r.x, s.y * inv + b.y + r.y);
    ((float2*)(out + (size_t)node * OUT_D))[lane] = o;
}

// ---------------- fused GEMM: layer1 (+bias+relu) and layer2 transform ----------------
__global__ void __launch_bounds__(256, 2) fused_gemm(const float* __restrict__ x,
                                                     const float* __restrict__ b1l) {
    extern __shared__ char sm[];
    uint32_t sbase = smem_u32(sm);
    const uint32_t Ah = sbase, Al = sbase + TS, Bs = sbase + 2 * TS;
    char* pAh = sm; char* pAl = sm + TS; char* pB = sm + 2 * TS;

    int tid = threadIdx.x;
    int lane = tid & 31, wid = tid >> 5;
    int tile0 = blockIdx.x * 128;
    int m_base = (wid & 3) * 32;
    int n_base = (wid >> 2) * 64;

    float acc[2][8][4];
#pragma unroll
    for (int i = 0; i < 2; i++)
#pragma unroll
        for (int j = 0; j < 8; j++)
#pragma unroll
            for (int c = 0; c < 4; c++) acc[i][j][c] = 0.f;

    // ---- layer 1, two phases: p0 = mean1 @ W1l, p1 = x @ W1r ----
    for (int p = 0; p < 2; p++) {
        const float* src = p ? x : g_mean1;
        for (int i = tid; i < 128 * 32; i += 256) {
            int r = i >> 5, c4 = (i & 31) << 2;
            int node = tile0 + r;
            float4 v = make_float4(0.f, 0.f, 0.f, 0.f);
            if (node < N_NODES)
                v = *(const float4*)(src + (size_t)node * D_FEAT + c4);
            split_store(pAh, pAl, (uint32_t)((r * LDA + c4) << 1), v);
        }
        const __nv_bfloat16* gBh = p ? g_W1r_hi : g_W1l_hi;
        const __nv_bfloat16* gBl = p ? g_W1r_lo : g_W1l_lo;
        for (int i = tid; i < 128 * 16; i += 256) {
            int r = i >> 4, c8 = (i & 15) << 3;
            *(uint4*)(pB + ((r * LDA + c8) << 1)) = *(const uint4*)(gBh + r * 128 + c8);
        }
        __syncthreads();
        mma_tile(Ah, Bs, acc, lane, m_base, n_base);
        mma_tile(Al, Bs, acc, lane, m_base, n_base);
        __syncthreads();
        for (int i = tid; i < 128 * 16; i += 256) {
            int r = i >> 4, c8 = (i & 15) << 3;
            *(uint4*)(pB + ((r * LDA + c8) << 1)) = *(const uint4*)(gBl + r * 128 + c8);
        }
        __syncthreads();
        mma_tile(Ah, Bs, acc, lane, m_base, n_base);
        __syncthreads();
    }

    // ---- epilogue 1: bias + relu, split hi/lo INTO smem A tiles ----
#pragma unroll
    for (int mi = 0; mi < 2; mi++) {
#pragma unroll
        for (int j = 0; j < 8; j++) {
            int col = n_base + j * 8 + (lane & 3) * 2;
            float2 bb = *(const float2*)(b1l + col);
            int r0 = m_base + mi * 16 + (lane >> 2);
#pragma unroll
            for (int half = 0; half < 2; half++) {
                int r = r0 + half * 8;
                float v0 = fmaxf(acc[mi][j][half * 2 + 0] + bb.x, 0.f);
                float v1 = fmaxf(acc[mi][j][half * 2 + 1] + bb.y, 0.f);
                __nv_bfloat16 h0 = __float2bfloat16(v0), h1 = __float2bfloat16(v1);
                __nv_bfloat162 ph; ph.x = h0; ph.y = h1;
                __nv_bfloat162 pl;
                pl.x = __float2bfloat16(v0 - __bfloat162float(h0));
                pl.y = __float2bfloat16(v1 - __bfloat162float(h1));
                uint32_t off = (uint32_t)((r * LDA + col) << 1);
                *(uint32_t*)(pAh + off) = *(uint32_t*)&ph;
                *(uint32_t*)(pAl + off) = *(uint32_t*)&pl;
            }
        }
    }
    // stage B = [W2l | W2r] hi
    for (int i = tid; i < 128 * 16; i += 256) {
        int r = i >> 4, c8 = (i & 15) << 3;
        *(uint4*)(pB + ((r * LDA + c8) << 1)) = *(const uint4*)(g_W2_hi + r * 128 + c8);
    }
    __syncthreads();

    // ---- layer 2 transform: [t | hr] = h @ [W2l | W2r] ----
#pragma unroll
    for (int i = 0; i < 2; i++)
#pragma unroll
        for (int j = 0; j < 8; j++)
#pragma unroll
            for (int c = 0; c < 4; c++) acc[i][j][c] = 0.f;

    mma_tile(Ah, Bs, acc, lane, m_base, n_base);
    mma_tile(Al, Bs, acc, lane, m_base, n_base);
    __syncthreads();
    for (int i = tid; i < 128 * 16; i += 256) {
        int r = i >> 4, c8 = (i & 15) << 3;
        *(uint4*)(pB + ((r * LDA + c8) << 1)) = *(const uint4*)(g_W2_lo + r * 128 + c8);
    }
    __syncthreads();
    mma_tile(Ah, Bs, acc, lane, m_base, n_base);

    // ---- epilogue 2: write t (cols 0-63) and hr (cols 64-127) ----
#pragma unroll
    for (int mi = 0; mi < 2; mi++) {
#pragma unroll
        for (int j = 0; j < 8; j++) {
            int col = n_base + j * 8 + (lane & 3) * 2;
            float* base = (col < 64) ? g_t : g_hr;
            int cc = col & 63;
            int r0 = m_base + mi * 16 + (lane >> 2);
#pragma unroll
            for (int half = 0; half < 2; half++) {
                int node = tile0 + r0 + half * 8;
                if (node < N_NODES) {
                    float2 v = make_float2(acc[mi][j][half * 2 + 0],
                                           acc[mi][j][half * 2 + 1]);
                    *(float2*)(base + (size_t)node * OUT_D + cc) = v;
                }
            }
        }
    }
}

// ---------------- launch ----------------
extern "C" void kernel_launch(void* const* d_in, const int* in_sizes, int n_in,
                              void* d_out, int out_size) {
    const float* x   = (const float*)d_in[0];
    const void*  ei  = d_in[1];
    const float* W1l = (const float*)d_in[2];
    const float* b1l = (const float*)d_in[3];
    const float* W1r = (const float*)d_in[4];
    const float* W2l = (const float*)d_in[5];
    const float* b2l = (const float*)d_in[6];
    const float* W2r = (const float*)d_in[7];
    float* out = (float*)d_out;
    int E = in_sizes[1] / 2;

    cudaFuncSetAttribute(fused_gemm, cudaFuncAttributeMaxDynamicSharedMemorySize, SM_TOTAL);

    init_kernel<<<(N_NODES + 255) / 256, 256>>>((const int*)ei);
    wprep_kernel<<<64, 256>>>(W1l, W1r, W2l, W2r);

    hist_kernel<<<(E + 255) / 256, 256>>>(ei, E);
    chunkred_kernel<<<NCHUNK, CHUNK>>>();
    chunkscan_kernel<<<1, 256>>>();
    rowptr_kernel<<<NCHUNK, CHUNK>>>();
    fill_kernel<<<(E + 255) / 256, 256>>>(ei, E);

    gather1_kernel<<<(N_NODES + 7) / 8, 256>>>(x);

    const int nTiles = (N_NODES + 127) / 128;   // 391
    fused_gemm<<<nTiles, 256, SM_TOTAL>>>(x, b1l);

    gather2_kernel<<<(N_NODES + 7) / 8, 256>>>(b2l, out);
}

// round 11
// speedup vs baseline: 1.0009x; 1.0009x over previous
#include <cuda_runtime.h>
#include <cuda_bf16.h>
#include <cstdint>

#define N_NODES 50000
#define N_EDGES_MAX 600000
#define D_FEAT 128
#define HIDDEN 128
#define OUT_D 64

#define LDA 136                      // padded bf16 row (128 + 8)
#define TS  (128 * LDA * 2)          // one smem tile: 34816 B
#define SM_TOTAL (3 * TS)            // Ah, Al, B = 104448 B -> 2 CTAs/SM

#define CHUNK 256
#define NCHUNK ((N_NODES + CHUNK - 1) / CHUNK)   // 196

// ---------------- device scratch (no allocs allowed) ----------------
__device__ float g_mean1[N_NODES * D_FEAT];   // layer-1 neighbor mean
__device__ float g_t[N_NODES * OUT_D];        // h @ W2l (pre-aggregation)
__device__ float g_hr[N_NODES * OUT_D];       // h @ W2r (root term)
__device__ int   g_is64;

// CSR structure (built per call, dst-sorted)
__device__ int g_deg[N_NODES];
__device__ int g_rowptr[N_NODES + 1];
__device__ int g_pos[N_NODES];
__device__ int g_csr_src[N_EDGES_MAX];
__device__ int g_chunksum[NCHUNK];
__device__ int g_chunkoff[NCHUNK];

// pre-split weights, [n][k] layout
__device__ __align__(16) __nv_bfloat16 g_W1l_hi[16384], g_W1l_lo[16384];
__device__ __align__(16) __nv_bfloat16 g_W1r_hi[16384], g_W1r_lo[16384];
__device__ __align__(16) __nv_bfloat16 g_W2_hi[16384],  g_W2_lo[16384];

// ---------------- helpers ----------------
__device__ __forceinline__ uint32_t smem_u32(const void* p) {
    uint32_t a;
    asm("{ .reg .u64 t; cvta.to.shared.u64 t, %1; cvt.u32.u64 %0, t; }"
        : "=r"(a) : "l"(p));
    return a;
}

__device__ __forceinline__ void ldm_x4(uint32_t* r, uint32_t addr) {
    asm volatile("ldmatrix.sync.aligned.m8n8.x4.shared.b16 {%0,%1,%2,%3}, [%4];"
                 : "=r"(r[0]), "=r"(r[1]), "=r"(r[2]), "=r"(r[3]) : "r"(addr));
}
__device__ __forceinline__ void mma16816(float* d, const uint32_t* a, const uint32_t* b) {
    asm volatile(
        "mma.sync.aligned.m16n8k16.row.col.f32.bf16.bf16.f32 "
        "{%0,%1,%2,%3},{%4,%5,%6,%7},{%8,%9},{%0,%1,%2,%3};"
        : "+f"(d[0]), "+f"(d[1]), "+f"(d[2]), "+f"(d[3])
        : "r"(a[0]), "r"(a[1]), "r"(a[2]), "r"(a[3]), "r"(b[0]), "r"(b[1]));
}

// one full K=128 pass of the 128x128 tile: warp (m_base, n_base) 32x64
__device__ __forceinline__ void mma_tile(uint32_t aBase, uint32_t bBase,
                                         float acc[2][8][4], int lane,
                                         int m_base, int n_base) {
    uint32_t aRow = aBase + (((m_base + (lane & 15)) * LDA + ((lane >> 4) << 3)) << 1);
    int bj = ((lane >> 4) & 1) * 8;
    int bk = ((lane >> 3) & 1) * 8;
    uint32_t bRow = bBase + (((n_base + bj + (lane & 7)) * LDA + bk) << 1);
#pragma unroll
    for (int k0 = 0; k0 < 128; k0 += 16) {
        uint32_t a0[4], a1[4];
        ldm_x4(a0, aRow + (k0 << 1));
        ldm_x4(a1, aRow + ((16 * LDA + k0) << 1));
        uint32_t b[8][2];
#pragma unroll
        for (int jp = 0; jp < 4; jp++) {
            uint32_t bb[4];
            ldm_x4(bb, bRow + ((jp * 16 * LDA + k0) << 1));
            b[jp * 2][0] = bb[0]; b[jp * 2][1] = bb[1];
            b[jp * 2 + 1][0] = bb[2]; b[jp * 2 + 1][1] = bb[3];
        }
#pragma unroll
        for (int j = 0; j < 8; j++) {
            mma16816(acc[0][j], a0, b[j]);
            mma16816(acc[1][j], a1, b[j]);
        }
    }
}

__device__ __forceinline__ void split_store(char* baseH, char* baseL, uint32_t off, float4 v) {
    __nv_bfloat162 h01, h23, l01, l23;
    __nv_bfloat16 h;
    h = __float2bfloat16(v.x); h01.x = h; l01.x = __float2bfloat16(v.x - __bfloat162float(h));
    h = __float2bfloat16(v.y); h01.y = h; l01.y = __float2bfloat16(v.y - __bfloat162float(h));
    h = __float2bfloat16(v.z); h23.x = h; l23.x = __float2bfloat16(v.z - __bfloat162float(h));
    h = __float2bfloat16(v.w); h23.y = h; l23.y = __float2bfloat16(v.w - __bfloat162float(h));
    *(uint2*)(baseH + off) = make_uint2(*(uint32_t*)&h01, *(uint32_t*)&h23);
    *(uint2*)(baseL + off) = make_uint2(*(uint32_t*)&l01, *(uint32_t*)&l23);
}

// ---------------- small kernels ----------------
__global__ void init_kernel(const int* __restrict__ idx) {
    int i = blockIdx.x * blockDim.x + threadIdx.x;
    if (i < N_NODES) g_deg[i] = 0;
    if (i == 0) {
        int ok = 1;
        for (int k = 0; k < 32; k++)
            if (idx[2 * k + 1] != 0) ok = 0;
        g_is64 = ok;
    }
}

__global__ void hist_kernel(const void* __restrict__ ei, int E) {
    int e = blockIdx.x * blockDim.x + threadIdx.x;
    if (e >= E) return;
    int d;
    if (g_is64) d = (int)((const long long*)ei)[E + e];
    else        d = ((const int*)ei)[E + e];
    atomicAdd(&g_deg[d], 1);
}

// ---- parallel 3-stage scan ----
// stage 1: per-chunk (256 degrees) sum
__global__ void chunkred_kernel() {
    __shared__ int sh[CHUNK];
    int i = blockIdx.x * CHUNK + threadIdx.x;
    sh[threadIdx.x] = (i < N_NODES) ? g_deg[i] : 0;
    __syncthreads();
    for (int off = CHUNK / 2; off > 0; off >>= 1) {
        if (threadIdx.x < off) sh[threadIdx.x] += sh[threadIdx.x + off];
        __syncthreads();
    }
    if (threadIdx.x == 0) g_chunksum[blockIdx.x] = sh[0];
}

// stage 2: single block scans NCHUNK chunk sums (exclusive)
__global__ void chunkscan_kernel() {
    __shared__ int sh[256];
    int t = threadIdx.x;
    sh[t] = (t < NCHUNK) ? g_chunksum[t] : 0;
    __syncthreads();
    for (int off = 1; off < 256; off <<= 1) {
        int v = (t >= off) ? sh[t - off] : 0;
        __syncthreads();
        sh[t] += v;
        __syncthreads();
    }
    if (t < NCHUNK) g_chunkoff[t] = (t == 0) ? 0 : sh[t - 1];
    if (t == 255) g_rowptr[N_NODES] = sh[NCHUNK - 1];
}

// stage 3: per-chunk exclusive scan + chunk offset -> rowptr, pos
__global__ void rowptr_kernel() {
    __shared__ int sh[CHUNK];
    int t = threadIdx.x;
    int i = blockIdx.x * CHUNK + t;
    int v = (i < N_NODES) ? g_deg[i] : 0;
    sh[t] = v;
    __syncthreads();
    for (int off = 1; off < CHUNK; off <<= 1) {
        int u = (t >= off) ? sh[t - off] : 0;
        __syncthreads();
        sh[t] += u;
        __syncthreads();
    }
    if (i < N_NODES) {
        int r = g_chunkoff[blockIdx.x] + sh[t] - v;   // exclusive
        g_rowptr[i] = r;
        g_pos[i] = r;
    }
}

__global__ void fill_kernel(const void* __restrict__ ei, int E) {
    int e = blockIdx.x * blockDim.x + threadIdx.x;
    if (e >= E) return;
    int s, d;
    if (g_is64) {
        const long long* p = (const long long*)ei;
        s = (int)p[e]; d = (int)p[E + e];
    } else {
        const int* p = (const int*)ei;
        s = p[e]; d = p[E + e];
    }
    int pos = atomicAdd(&g_pos[d], 1);
    g_csr_src[pos] = s;
}

__global__ void wprep_kernel(const float* __restrict__ W1l, const float* __restrict__ W1r,
                             const float* __restrict__ W2l, const float* __restrict__ W2r) {
    int i = blockIdx.x * blockDim.x + threadIdx.x;
    if (i >= 16384) return;
    int n = i >> 7, k = i & 127;
    float v = W1l[k * 128 + n];
    __nv_bfloat16 h = __float2bfloat16(v);
    g_W1l_hi[i] = h; g_W1l_lo[i] = __float2bfloat16(v - __bfloat162float(h));
    v = W1r[k * 128 + n];
    h = __float2bfloat16(v);
    g_W1r_hi[i] = h; g_W1r_lo[i] = __float2bfloat16(v - __bfloat162float(h));
    v = (n < 64) ? W2l[k * 64 + n] : W2r[k * 64 + (n - 64)];
    h = __float2bfloat16(v);
    g_W2_hi[i] = h; g_W2_lo[i] = __float2bfloat16(v - __bfloat162float(h));
}

// ---------------- gather-aggregate layer 1: warp per node, writes mean ----------------
__global__ void __launch_bounds__(256) gather1_kernel(const float* __restrict__ x) {
    int node = blockIdx.x * 8 + (threadIdx.x >> 5);
    if (node >= N_NODES) return;
    int lane = threadIdx.x & 31;
    int beg = g_rowptr[node], end = g_rowptr[node + 1];
    float4 s = make_float4(0.f, 0.f, 0.f, 0.f);
    int e = beg;
    for (; e + 2 <= end; e += 2) {
        int s0 = g_csr_src[e], s1 = g_csr_src[e + 1];
        float4 v0 = ((const float4*)(x + (size_t)s0 * D_FEAT))[lane];
        float4 v1 = ((const float4*)(x + (size_t)s1 * D_FEAT))[lane];
        s.x += v0.x + v1.x; s.y += v0.y + v1.y;
        s.z += v0.z + v1.z; s.w += v0.w + v1.w;
    }
    if (e < end) {
        int s0 = g_csr_src[e];
        float4 v0 = ((const float4*)(x + (size_t)s0 * D_FEAT))[lane];
        s.x += v0.x; s.y += v0.y; s.z += v0.z; s.w += v0.w;
    }
    float inv = 1.0f / (float)max(end - beg, 1);
    ((float4*)(g_mean1 + (size_t)node * D_FEAT))[lane] =
        make_float4(s.x * inv, s.y * inv, s.z * inv, s.w * inv);
}

// ---------------- gather-aggregate layer 2 + final epilogue ----------------
__global__ void __launch_bounds__(256) gather2_kernel(const float* __restrict__ b2l,
                                                      float* __restrict__ out) {
    int node = blockIdx.x * 8 + (threadIdx.x >> 5);
    if (node >= N_NODES) return;
    int lane = threadIdx.x & 31;
    int beg = g_rowptr[node], end = g_rowptr[node + 1];
    float2 s = make_float2(0.f, 0.f);
    int e = beg;
    for (; e + 2 <= end; e += 2) {
        int s0 = g_csr_src[e], s1 = g_csr_src[e + 1];
        float2 v0 = ((const float2*)(g_t + (size_t)s0 * OUT_D))[lane];
        float2 v1 = ((const float2*)(g_t + (size_t)s1 * OUT_D))[lane];
        s.x += v0.x + v1.x; s.y += v0.y + v1.y;
    }
    if (e < end) {
        int s0 = g_csr_src[e];
        float2 v0 = ((const float2*)(g_t + (size_t)s0 * OUT_D))[lane];
        s.x += v0.x; s.y += v0.y;
    }
    float inv = 1.0f / (float)max(end - beg, 1);
    float2 r = ((const float2*)(g_hr + (size_t)node * OUT_D))[lane];
    float2 b = ((const float2*)b2l)[lane];
    float2 o = make_float2(s.x * inv + b.x + r.x, s.y * inv + b.y + r.y);
    ((float2*)(out + (size_t)node * OUT_D))[lane] = o;
}

// ---------------- fused GEMM: layer1 (+bias+relu) and layer2 transform ----------------
__global__ void __launch_bounds__(256, 2) fused_gemm(const float* __restrict__ x,
                                                     const float* __restrict__ b1l) {
    extern __shared__ char sm[];
    uint32_t sbase = smem_u32(sm);
    const uint32_t Ah = sbase, Al = sbase + TS, Bs = sbase + 2 * TS;
    char* pAh = sm; char* pAl = sm + TS; char* pB = sm + 2 * TS;

    int tid = threadIdx.x;
    int lane = tid & 31, wid = tid >> 5;
    int tile0 = blockIdx.x * 128;
    int m_base = (wid & 3) * 32;
    int n_base = (wid >> 2) * 64;

    float acc[2][8][4];
#pragma unroll
    for (int i = 0; i < 2; i++)
#pragma unroll
        for (int j = 0; j < 8; j++)
#pragma unroll
            for (int c = 0; c < 4; c++) acc[i][j][c] = 0.f;

    // ---- layer 1, two phases: p0 = mean1 @ W1l, p1 = x @ W1r ----
    for (int p = 0; p < 2; p++) {
        const float* src = p ? x : g_mean1;
        for (int i = tid; i < 128 * 32; i += 256) {
            int r = i >> 5, c4 = (i & 31) << 2;
            int node = tile0 + r;
            float4 v = make_float4(0.f, 0.f, 0.f, 0.f);
            if (node < N_NODES)
                v = *(const float4*)(src + (size_t)node * D_FEAT + c4);
            split_store(pAh, pAl, (uint32_t)((r * LDA + c4) << 1), v);
        }
        const __nv_bfloat16* gBh = p ? g_W1r_hi : g_W1l_hi;
        const __nv_bfloat16* gBl = p ? g_W1r_lo : g_W1l_lo;
        for (int i = tid; i < 128 * 16; i += 256) {
            int r = i >> 4, c8 = (i & 15) << 3;
            *(uint4*)(pB + ((r * LDA + c8) << 1)) = *(const uint4*)(gBh + r * 128 + c8);
        }
        __syncthreads();
        mma_tile(Ah, Bs, acc, lane, m_base, n_base);
        mma_tile(Al, Bs, acc, lane, m_base, n_base);
        __syncthreads();
        for (int i = tid; i < 128 * 16; i += 256) {
            int r = i >> 4, c8 = (i & 15) << 3;
            *(uint4*)(pB + ((r * LDA + c8) << 1)) = *(const uint4*)(gBl + r * 128 + c8);
        }
        __syncthreads();
        mma_tile(Ah, Bs, acc, lane, m_base, n_base);
        __syncthreads();
    }

    // ---- epilogue 1: bias + relu, split hi/lo INTO smem A tiles ----
#pragma unroll
    for (int mi = 0; mi < 2; mi++) {
#pragma unroll
        for (int j = 0; j < 8; j++) {
            int col = n_base + j * 8 + (lane & 3) * 2;
            float2 bb = *(const float2*)(b1l + col);
            int r0 = m_base + mi * 16 + (lane >> 2);
#pragma unroll
            for (int half = 0; half < 2; half++) {
                int r = r0 + half * 8;
                float v0 = fmaxf(acc[mi][j][half * 2 + 0] + bb.x, 0.f);
                float v1 = fmaxf(acc[mi][j][half * 2 + 1] + bb.y, 0.f);
                __nv_bfloat16 h0 = __float2bfloat16(v0), h1 = __float2bfloat16(v1);
                __nv_bfloat162 ph; ph.x = h0; ph.y = h1;
                __nv_bfloat162 pl;
                pl.x = __float2bfloat16(v0 - __bfloat162float(h0));
                pl.y = __float2bfloat16(v1 - __bfloat162float(h1));
                uint32_t off = (uint32_t)((r * LDA + col) << 1);
                *(uint32_t*)(pAh + off) = *(uint32_t*)&ph;
                *(uint32_t*)(pAl + off) = *(uint32_t*)&pl;
            }
        }
    }
    // stage B = [W2l | W2r] hi
    for (int i = tid; i < 128 * 16; i += 256) {
        int r = i >> 4, c8 = (i & 15) << 3;
        *(uint4*)(pB + ((r * LDA + c8) << 1)) = *(const uint4*)(g_W2_hi + r * 128 + c8);
    }
    __syncthreads();

    // ---- layer 2 transform: [t | hr] = h @ [W2l | W2r] ----
#pragma unroll
    for (int i = 0; i < 2; i++)
#pragma unroll
        for (int j = 0; j < 8; j++)
#pragma unroll
            for (int c = 0; c < 4; c++) acc[i][j][c] = 0.f;

    mma_tile(Ah, Bs, acc, lane, m_base, n_base);
    mma_tile(Al, Bs, acc, lane, m_base, n_base);
    __syncthreads();
    for (int i = tid; i < 128 * 16; i += 256) {
        int r = i >> 4, c8 = (i & 15) << 3;
        *(uint4*)(pB + ((r * LDA + c8) << 1)) = *(const uint4*)(g_W2_lo + r * 128 + c8);
    }
    __syncthreads();
    mma_tile(Ah, Bs, acc, lane, m_base, n_base);

    // ---- epilogue 2: write t (cols 0-63) and hr (cols 64-127) ----
#pragma unroll
    for (int mi = 0; mi < 2; mi++) {
#pragma unroll
        for (int j = 0; j < 8; j++) {
            int col = n_base + j * 8 + (lane & 3) * 2;
            float* base = (col < 64) ? g_t : g_hr;
            int cc = col & 63;
            int r0 = m_base + mi * 16 + (lane >> 2);
#pragma unroll
            for (int half = 0; half < 2; half++) {
                int node = tile0 + r0 + half * 8;
                if (node < N_NODES) {
                    float2 v = make_float2(acc[mi][j][half * 2 + 0],
                                           acc[mi][j][half * 2 + 1]);
                    *(float2*)(base + (size_t)node * OUT_D + cc) = v;
                }
            }
        }
    }
}

// ---------------- launch ----------------
extern "C" void kernel_launch(void* const* d_in, const int* in_sizes, int n_in,
                              void* d_out, int out_size) {
    const float* x   = (const float*)d_in[0];
    const void*  ei  = d_in[1];
    const float* W1l = (const float*)d_in[2];
    const float* b1l = (const float*)d_in[3];
    const float* W1r = (const float*)d_in[4];
    const float* W2l = (const float*)d_in[5];
    const float* b2l = (const float*)d_in[6];
    const float* W2r = (const float*)d_in[7];
    float* out = (float*)d_out;
    int E = in_sizes[1] / 2;

    cudaFuncSetAttribute(fused_gemm, cudaFuncAttributeMaxDynamicSharedMemorySize, SM_TOTAL);

    init_kernel<<<(N_NODES + 255) / 256, 256>>>((const int*)ei);
    wprep_kernel<<<64, 256>>>(W1l, W1r, W2l, W2r);

    hist_kernel<<<(E + 255) / 256, 256>>>(ei, E);
    chunkred_kernel<<<NCHUNK, CHUNK>>>();
    chunkscan_kernel<<<1, 256>>>();
    rowptr_kernel<<<NCHUNK, CHUNK>>>();
    fill_kernel<<<(E + 255) / 256, 256>>>(ei, E);

    gather1_kernel<<<(N_NODES + 7) / 8, 256>>>(x);

    const int nTiles = (N_NODES + 127) / 128;   // 391
    fused_gemm<<<nTiles, 256, SM_TOTAL>>>(x, b1l);

    gather2_kernel<<<(N_NODES + 7) / 8, 256>>>(b2l, out);
}

// round 12
// speedup vs baseline: 1.0045x; 1.0036x over previous
#include <cuda_runtime.h>
#include <cuda_bf16.h>
#include <cstdint>

#define N_NODES 50000
#define N_EDGES_MAX 600000
#define D_FEAT 128
#define HIDDEN 128
#define OUT_D 64

#define LDA 136                      // padded bf16 row (128 + 8)
#define TS  (128 * LDA * 2)          // one smem tile: 34816 B
#define SM_TOTAL (3 * TS)            // Ah, Al, B = 104448 B -> 2 CTAs/SM

#define CHUNK 256
#define NCHUNK ((N_NODES + CHUNK - 1) / CHUNK)   // 196

// ---------------- device scratch (no allocs allowed) ----------------
__device__ float g_mean1[N_NODES * D_FEAT];   // layer-1 neighbor mean
__device__ float g_t[N_NODES * OUT_D];        // h @ W2l (pre-aggregation)
__device__ float g_hr[N_NODES * OUT_D];       // h @ W2r (root term)
__device__ int   g_is64;

// CSR structure (built per call, dst-sorted)
__device__ int g_deg[N_NODES];
__device__ int g_rowptr[N_NODES + 1];
__device__ int g_pos[N_NODES];
__device__ int g_csr_src[N_EDGES_MAX];
__device__ int g_chunksum[NCHUNK];
__device__ int g_chunkoff[NCHUNK];

// pre-split weights, [n][k] layout
__device__ __align__(16) __nv_bfloat16 g_W1l_hi[16384], g_W1l_lo[16384];
__device__ __align__(16) __nv_bfloat16 g_W1r_hi[16384], g_W1r_lo[16384];
__device__ __align__(16) __nv_bfloat16 g_W2_hi[16384],  g_W2_lo[16384];

// ---------------- helpers ----------------
__device__ __forceinline__ uint32_t smem_u32(const void* p) {
    uint32_t a;
    asm("{ .reg .u64 t; cvta.to.shared.u64 t, %1; cvt.u32.u64 %0, t; }"
        : "=r"(a) : "l"(p));
    return a;
}

__device__ __forceinline__ void ldm_x4(uint32_t* r, uint32_t addr) {
    asm volatile("ldmatrix.sync.aligned.m8n8.x4.shared.b16 {%0,%1,%2,%3}, [%4];"
                 : "=r"(r[0]), "=r"(r[1]), "=r"(r[2]), "=r"(r[3]) : "r"(addr));
}
__device__ __forceinline__ void mma16816(float* d, const uint32_t* a, const uint32_t* b) {
    asm volatile(
        "mma.sync.aligned.m16n8k16.row.col.f32.bf16.bf16.f32 "
        "{%0,%1,%2,%3},{%4,%5,%6,%7},{%8,%9},{%0,%1,%2,%3};"
        : "+f"(d[0]), "+f"(d[1]), "+f"(d[2]), "+f"(d[3])
        : "r"(a[0]), "r"(a[1]), "r"(a[2]), "r"(a[3]), "r"(b[0]), "r"(b[1]));
}

// one full K=128 pass of the 128x128 tile: warp (m_base, n_base) 32x64
__device__ __forceinline__ void mma_tile(uint32_t aBase, uint32_t bBase,
                                         float acc[2][8][4], int lane,
                                         int m_base, int n_base) {
    uint32_t aRow = aBase + (((m_base + (lane & 15)) * LDA + ((lane >> 4) << 3)) << 1);
    int bj = ((lane >> 4) & 1) * 8;
    int bk = ((lane >> 3) & 1) * 8;
    uint32_t bRow = bBase + (((n_base + bj + (lane & 7)) * LDA + bk) << 1);
#pragma unroll
    for (int k0 = 0; k0 < 128; k0 += 16) {
        uint32_t a0[4], a1[4];
        ldm_x4(a0, aRow + (k0 << 1));
        ldm_x4(a1, aRow + ((16 * LDA + k0) << 1));
        uint32_t b[8][2];
#pragma unroll
        for (int jp = 0; jp < 4; jp++) {
            uint32_t bb[4];
            ldm_x4(bb, bRow + ((jp * 16 * LDA + k0) << 1));
            b[jp * 2][0] = bb[0]; b[jp * 2][1] = bb[1];
            b[jp * 2 + 1][0] = bb[2]; b[jp * 2 + 1][1] = bb[3];
        }
#pragma unroll
        for (int j = 0; j < 8; j++) {
            mma16816(acc[0][j], a0, b[j]);
            mma16816(acc[1][j], a1, b[j]);
        }
    }
}

__device__ __forceinline__ void split_store(char* baseH, char* baseL, uint32_t off, float4 v) {
    __nv_bfloat162 h01, h23, l01, l23;
    __nv_bfloat16 h;
    h = __float2bfloat16(v.x); h01.x = h; l01.x = __float2bfloat16(v.x - __bfloat162float(h));
    h = __float2bfloat16(v.y); h01.y = h; l01.y = __float2bfloat16(v.y - __bfloat162float(h));
    h = __float2bfloat16(v.z); h23.x = h; l23.x = __float2bfloat16(v.z - __bfloat162float(h));
    h = __float2bfloat16(v.w); h23.y = h; l23.y = __float2bfloat16(v.w - __bfloat162float(h));
    *(uint2*)(baseH + off) = make_uint2(*(uint32_t*)&h01, *(uint32_t*)&h23);
    *(uint2*)(baseL + off) = make_uint2(*(uint32_t*)&l01, *(uint32_t*)&l23);
}

// ---------------- small kernels ----------------
__global__ void init_kernel(const int* __restrict__ idx) {
    int i = blockIdx.x * blockDim.x + threadIdx.x;
    if (i < N_NODES) g_deg[i] = 0;
    if (i == 0) {
        int ok = 1;
        for (int k = 0; k < 32; k++)
            if (idx[2 * k + 1] != 0) ok = 0;
        g_is64 = ok;
    }
}

__global__ void hist_kernel(const void* __restrict__ ei, int E) {
    int e = blockIdx.x * blockDim.x + threadIdx.x;
    if (e >= E) return;
    int d;
    if (g_is64) d = (int)((const long long*)ei)[E + e];
    else        d = ((const int*)ei)[E + e];
    atomicAdd(&g_deg[d], 1);
}

// ---- parallel 3-stage scan ----
// stage 1: per-chunk (256 degrees) sum
__global__ void chunkred_kernel() {
    __shared__ int sh[CHUNK];
    int i = blockIdx.x * CHUNK + threadIdx.x;
    sh[threadIdx.x] = (i < N_NODES) ? g_deg[i] : 0;
    __syncthreads();
    for (int off = CHUNK / 2; off > 0; off >>= 1) {
        if (threadIdx.x < off) sh[threadIdx.x] += sh[threadIdx.x + off];
        __syncthreads();
    }
    if (threadIdx.x == 0) g_chunksum[blockIdx.x] = sh[0];
}

// stage 2: single block scans NCHUNK chunk sums (exclusive)
__global__ void chunkscan_kernel() {
    __shared__ int sh[256];
    int t = threadIdx.x;
    sh[t] = (t < NCHUNK) ? g_chunksum[t] : 0;
    __syncthreads();
    for (int off = 1; off < 256; off <<= 1) {
        int v = (t >= off) ? sh[t - off] : 0;
        __syncthreads();
        sh[t] += v;
        __syncthreads();
    }
    if (t < NCHUNK) g_chunkoff[t] = (t == 0) ? 0 : sh[t - 1];
    if (t == 255) g_rowptr[N_NODES] = sh[NCHUNK - 1];
}

// stage 3: per-chunk exclusive scan + chunk offset -> rowptr, pos
__global__ void rowptr_kernel() {
    __shared__ int sh[CHUNK];
    int t = threadIdx.x;
    int i = blockIdx.x * CHUNK + t;
    int v = (i < N_NODES) ? g_deg[i] : 0;
    sh[t] = v;
    __syncthreads();
    for (int off = 1; off < CHUNK; off <<= 1) {
        int u = (t >= off) ? sh[t - off] : 0;
        __syncthreads();
        sh[t] += u;
        __syncthreads();
    }
    if (i < N_NODES) {
        int r = g_chunkoff[blockIdx.x] + sh[t] - v;   // exclusive
        g_rowptr[i] = r;
        g_pos[i] = r;
    }
}

__global__ void fill_kernel(const void* __restrict__ ei, int E) {
    int e = blockIdx.x * blockDim.x + threadIdx.x;
    if (e >= E) return;
    int s, d;
    if (g_is64) {
        const long long* p = (const long long*)ei;
        s = (int)p[e]; d = (int)p[E + e];
    } else {
        const int* p = (const int*)ei;
        s = p[e]; d = p[E + e];
    }
    int pos = atomicAdd(&g_pos[d], 1);
    g_csr_src[pos] = s;
}

__global__ void wprep_kernel(const float* __restrict__ W1l, const float* __restrict__ W1r,
                             const float* __restrict__ W2l, const float* __restrict__ W2r) {
    int i = blockIdx.x * blockDim.x + threadIdx.x;
    if (i >= 16384) return;
    int n = i >> 7, k = i & 127;
    float v = W1l[k * 128 + n];
    __nv_bfloat16 h = __float2bfloat16(v);
    g_W1l_hi[i] = h; g_W1l_lo[i] = __float2bfloat16(v - __bfloat162float(h));
    v = W1r[k * 128 + n];
    h = __float2bfloat16(v);
    g_W1r_hi[i] = h; g_W1r_lo[i] = __float2bfloat16(v - __bfloat162float(h));
    v = (n < 64) ? W2l[k * 64 + n] : W2r[k * 64 + (n - 64)];
    h = __float2bfloat16(v);
    g_W2_hi[i] = h; g_W2_lo[i] = __float2bfloat16(v - __bfloat162float(h));
}

// ---------------- gather-aggregate layer 1: warp per node, writes mean ----------------
__global__ void __launch_bounds__(256) gather1_kernel(const float* __restrict__ x) {
    int node = blockIdx.x * 8 + (threadIdx.x >> 5);
    if (node >= N_NODES) return;
    int lane = threadIdx.x & 31;
    int beg = g_rowptr[node], end = g_rowptr[node + 1];
    float4 s = make_float4(0.f, 0.f, 0.f, 0.f);
    int e = beg;
    for (; e + 2 <= end; e += 2) {
        int s0 = g_csr_src[e], s1 = g_csr_src[e + 1];
        float4 v0 = ((const float4*)(x + (size_t)s0 * D_FEAT))[lane];
        float4 v1 = ((const float4*)(x + (size_t)s1 * D_FEAT))[lane];
        s.x += v0.x + v1.x; s.y += v0.y + v1.y;
        s.z += v0.z + v1.z; s.w += v0.w + v1.w;
    }
    if (e < end) {
        int s0 = g_csr_src[e];
        float4 v0 = ((const float4*)(x + (size_t)s0 * D_FEAT))[lane];
        s.x += v0.x; s.y += v0.y; s.z += v0.z; s.w += v0.w;
    }
    float inv = 1.0f / (float)max(end - beg, 1);
    ((float4*)(g_mean1 + (size_t)node * D_FEAT))[lane] =
        make_float4(s.x * inv, s.y * inv, s.z * inv, s.w * inv);
}

// ---------------- gather-aggregate layer 2 + final epilogue ----------------
__global__ void __launch_bounds__(256) gather2_kernel(const float* __restrict__ b2l,
                                                      float* __restrict__ out) {
    int node = blockIdx.x * 8 + (threadIdx.x >> 5);
    if (node >= N_NODES) return;
    int lane = threadIdx.x & 31;
    int beg = g_rowptr[node], end = g_rowptr[node + 1];
    float2 s = make_float2(0.f, 0.f);
    int e = beg;
    for (; e + 2 <= end; e += 2) {
        int s0 = g_csr_src[e], s1 = g_csr_src[e + 1];
        float2 v0 = ((const float2*)(g_t + (size_t)s0 * OUT_D))[lane];
        float2 v1 = ((const float2*)(g_t + (size_t)s1 * OUT_D))[lane];
        s.x += v0.x + v1.x; s.y += v0.y + v1.y;
    }
    if (e < end) {
        int s0 = g_csr_src[e];
        float2 v0 = ((const float2*)(g_t + (size_t)s0 * OUT_D))[lane];
        s.x += v0.x; s.y += v0.y;
    }
    float inv = 1.0f / (float)max(end - beg, 1);
    float2 r = ((const float2*)(g_hr + (size_t)node * OUT_D))[lane];
    float2 b = ((const float2*)b2l)[lane];
    float2 o = make_float2(s.x * inv + b.x + r.x, s.y * inv + b.y + r.y);
    ((float2*)(out + (size_t)node * OUT_D))[lane] = o;
}

// ---------------- fused GEMM: layer1 (+bias+relu) and layer2 transform ----------------
__global__ void __launch_bounds__(256, 2) fused_gemm(const float* __restrict__ x,
                                                     const float* __restrict__ b1l) {
    extern __shared__ char sm[];
    uint32_t sbase = smem_u32(sm);
    const uint32_t Ah = sbase, Al = sbase + TS, Bs = sbase + 2 * TS;
    char* pAh = sm; char* pAl = sm + TS; char* pB = sm + 2 * TS;

    int tid = threadIdx.x;
    int lane = tid & 31, wid = tid >> 5;
    int tile0 = blockIdx.x * 128;
    int m_base = (wid & 3) * 32;
    int n_base = (wid >> 2) * 64;

    float acc[2][8][4];
#pragma unroll
    for (int i = 0; i < 2; i++)
#pragma unroll
        for (int j = 0; j < 8; j++)
#pragma unroll
            for (int c = 0; c < 4; c++) acc[i][j][c] = 0.f;

    // ---- layer 1, two phases: p0 = mean1 @ W1l, p1 = x @ W1r ----
    for (int p = 0; p < 2; p++) {
        const float* src = p ? x : g_mean1;
        for (int i = tid; i < 128 * 32; i += 256) {
            int r = i >> 5, c4 = (i & 31) << 2;
            int node = tile0 + r;
            float4 v = make_float4(0.f, 0.f, 0.f, 0.f);
            if (node < N_NODES)
                v = *(const float4*)(src + (size_t)node * D_FEAT + c4);
            split_store(pAh, pAl, (uint32_t)((r * LDA + c4) << 1), v);
        }
        const __nv_bfloat16* gBh = p ? g_W1r_hi : g_W1l_hi;
        const __nv_bfloat16* gBl = p ? g_W1r_lo : g_W1l_lo;
        for (int i = tid; i < 128 * 16; i += 256) {
            int r = i >> 4, c8 = (i & 15) << 3;
            *(uint4*)(pB + ((r * LDA + c8) << 1)) = *(const uint4*)(gBh + r * 128 + c8);
        }
        __syncthreads();
        mma_tile(Ah, Bs, acc, lane, m_base, n_base);
        mma_tile(Al, Bs, acc, lane, m_base, n_base);
        __syncthreads();
        for (int i = tid; i < 128 * 16; i += 256) {
            int r = i >> 4, c8 = (i & 15) << 3;
            *(uint4*)(pB + ((r * LDA + c8) << 1)) = *(const uint4*)(gBl + r * 128 + c8);
        }
        __syncthreads();
        mma_tile(Ah, Bs, acc, lane, m_base, n_base);
        __syncthreads();
    }

    // ---- epilogue 1: bias + relu, split hi/lo INTO smem A tiles ----
#pragma unroll
    for (int mi = 0; mi < 2; mi++) {
#pragma unroll
        for (int j = 0; j < 8; j++) {
            int col = n_base + j * 8 + (lane & 3) * 2;
            float2 bb = *(const float2*)(b1l + col);
            int r0 = m_base + mi * 16 + (lane >> 2);
#pragma unroll
            for (int half = 0; half < 2; half++) {
                int r = r0 + half * 8;
                float v0 = fmaxf(acc[mi][j][half * 2 + 0] + bb.x, 0.f);
                float v1 = fmaxf(acc[mi][j][half * 2 + 1] + bb.y, 0.f);
                __nv_bfloat16 h0 = __float2bfloat16(v0), h1 = __float2bfloat16(v1);
                __nv_bfloat162 ph; ph.x = h0; ph.y = h1;
                __nv_bfloat162 pl;
                pl.x = __float2bfloat16(v0 - __bfloat162float(h0));
                pl.y = __float2bfloat16(v1 - __bfloat162float(h1));
                uint32_t off = (uint32_t)((r * LDA + col) << 1);
                *(uint32_t*)(pAh + off) = *(uint32_t*)&ph;
                *(uint32_t*)(pAl + off) = *(uint32_t*)&pl;
            }
        }
    }
    // stage B = [W2l | W2r] hi
    for (int i = tid; i < 128 * 16; i += 256) {
        int r = i >> 4, c8 = (i & 15) << 3;
        *(uint4*)(pB + ((r * LDA + c8) << 1)) = *(const uint4*)(g_W2_hi + r * 128 + c8);
    }
    __syncthreads();

    // ---- layer 2 transform: [t | hr] = h @ [W2l | W2r] ----
#pragma unroll
    for (int i = 0; i < 2; i++)
#pragma unroll
        for (int j = 0; j < 8; j++)
#pragma unroll
            for (int c = 0; c < 4; c++) acc[i][j][c] = 0.f;

    mma_tile(Ah, Bs, acc, lane, m_base, n_base);
    mma_tile(Al, Bs, acc, lane, m_base, n_base);
    __syncthreads();
    for (int i = tid; i < 128 * 16; i += 256) {
        int r = i >> 4, c8 = (i & 15) << 3;
        *(uint4*)(pB + ((r * LDA + c8) << 1)) = *(const uint4*)(g_W2_lo + r * 128 + c8);
    }
    __syncthreads();
    mma_tile(Ah, Bs, acc, lane, m_base, n_base);

    // ---- epilogue 2: write t (cols 0-63) and hr (cols 64-127) ----
#pragma unroll
    for (int mi = 0; mi < 2; mi++) {
#pragma unroll
        for (int j = 0; j < 8; j++) {
            int col = n_base + j * 8 + (lane & 3) * 2;
            float* base = (col < 64) ? g_t : g_hr;
            int cc = col & 63;
            int r0 = m_base + mi * 16 + (lane >> 2);
#pragma unroll
            for (int half = 0; half < 2; half++) {
                int node = tile0 + r0 + half * 8;
                if (node < N_NODES) {
                    float2 v = make_float2(acc[mi][j][half * 2 + 0],
                                           acc[mi][j][half * 2 + 1]);
                    *(float2*)(base + (size_t)node * OUT_D + cc) = v;
                }
            }
        }
    }
}

// ---------------- launch ----------------
extern "C" void kernel_launch(void* const* d_in, const int* in_sizes, int n_in,
                              void* d_out, int out_size) {
    const float* x   = (const float*)d_in[0];
    const void*  ei  = d_in[1];
    const float* W1l = (const float*)d_in[2];
    const float* b1l = (const float*)d_in[3];
    const float* W1r = (const float*)d_in[4];
    const float* W2l = (const float*)d_in[5];
    const float* b2l = (const float*)d_in[6];
    const float* W2r = (const float*)d_in[7];
    float* out = (float*)d_out;
    int E = in_sizes[1] / 2;

    cudaFuncSetAttribute(fused_gemm, cudaFuncAttributeMaxDynamicSharedMemorySize, SM_TOTAL);

    init_kernel<<<(N_NODES + 255) / 256, 256>>>((const int*)ei);
    wprep_kernel<<<64, 256>>>(W1l, W1r, W2l, W2r);

    hist_kernel<<<(E + 255) / 256, 256>>>(ei, E);
    chunkred_kernel<<<NCHUNK, CHUNK>>>();
    chunkscan_kernel<<<1, 256>>>();
    rowptr_kernel<<<NCHUNK, CHUNK>>>();
    fill_kernel<<<(E + 255) / 256, 256>>>(ei, E);

    gather1_kernel<<<(N_NODES + 7) / 8, 256>>>(x);

    const int nTiles = (N_NODES + 127) / 128;   // 391
    fused_gemm<<<nTiles, 256, SM_TOTAL>>>(x, b1l);

    gather2_kernel<<<(N_NODES + 7) / 8, 256>>>(b2l, out);
}